// round 14
// baseline (speedup 1.0000x reference)
#include <cuda_runtime.h>
#include <cuda_bf16.h>
#include <math.h>
#include <stdint.h>

#define NN   40000
#define EE   640000
#define DD   128
#define HH   8
#define LL   3
#define IND  64
#define FFD  218
#define FFP  224
#define CATD 512
#define EPSV 1e-5f
#define NEG_SLOPE 0.2f

// ---------------- device scratch ----------------
__device__ __align__(256) float g_Xcat[NN * CATD];
__device__ __align__(256) float g_feat[NN * DD];
__device__ __align__(256) float g_el[NN * HH];
__device__ __align__(256) float g_er[NN * HH];
__device__ __align__(256) float g_h1[NN * DD];
__device__ __align__(256) float g_h2[NN * DD];
__device__ __align__(256) float g_z [NN * DD];
__device__ __align__(256) float g_stats[256];   // zero-init; k_bncoef re-zeroes after use
__device__ __align__(256) float g_coef[256];
__device__ int g_deg[NN];
__device__ int g_rowptr[NN + 1];
__device__ int g_wp[NN];
__device__ int g_csr_src[EE];

// bf16 hi/lo operand buffers
__device__ __align__(256) __nv_bfloat16 gb_xh[NN * IND],   gb_xl[NN * IND];
__device__ __align__(256) __nv_bfloat16 gb_Xh[NN * CATD],  gb_Xl[NN * CATD];
__device__ __align__(256) __nv_bfloat16 gb_hbh[NN * DD],   gb_hbl[NN * DD];
__device__ __align__(256) __nv_bfloat16 gb_th[NN * FFP],   gb_tl[NN * FFP];
__device__ __align__(256) __nv_bfloat16 gb_WembT_h[DD * IND],     gb_WembT_l[DD * IND];
__device__ __align__(256) __nv_bfloat16 gb_gatWT_h[LL * DD * DD], gb_gatWT_l[LL * DD * DD];
__device__ __align__(256) __nv_bfloat16 gb_W1T_h[LL * FFP * DD],  gb_W1T_l[LL * FFP * DD];
__device__ __align__(256) __nv_bfloat16 gb_W2T_h[LL * DD * FFP],  gb_W2T_l[LL * DD * FFP];
__device__ __align__(256) __nv_bfloat16 gb_dW1T_h[DD * CATD],     gb_dW1T_l[DD * CATD];

// ---------------- CSR build ----------------
__global__ void k_zero_deg() {
    int i = blockIdx.x * 256 + threadIdx.x;
    if (i < NN) g_deg[i] = 0;
}
__global__ void k_hist(const int* __restrict__ dst) {
    int e = blockIdx.x * 256 + threadIdx.x;
    if (e < EE) atomicAdd(&g_deg[dst[e]], 1);
}
__global__ void k_scan() {
    __shared__ int sm[1024];
    const int tid = threadIdx.x;
    const int C = (NN + 1023) / 1024;   // 40
    const int base = tid * C;
    int s = 0;
    for (int j = 0; j < C; j++) {
        int i = base + j;
        if (i < NN) s += g_deg[i];
    }
    sm[tid] = s;
    __syncthreads();
    for (int off = 1; off < 1024; off <<= 1) {
        int v = (tid >= off) ? sm[tid - off] : 0;
        __syncthreads();
        sm[tid] += v;
        __syncthreads();
    }
    int run = sm[tid] - s;
    for (int j = 0; j < C; j++) {
        int i = base + j;
        if (i < NN) {
            g_rowptr[i] = run;
            g_wp[i] = run;
            run += g_deg[i];
        }
    }
    if (tid == 0) g_rowptr[NN] = EE;
}
__global__ void k_scatter(const int* __restrict__ src, const int* __restrict__ dst) {
    int e = blockIdx.x * 256 + threadIdx.x;
    if (e < EE) {
        int p = atomicAdd(&g_wp[dst[e]], 1);
        g_csr_src[p] = src[e];
    }
}

// ---------------- conversions ----------------
__global__ void k_cvt(const float* __restrict__ src, __nv_bfloat16* __restrict__ oh,
                      __nv_bfloat16* __restrict__ ol, int n) {
    int i = blockIdx.x * 256 + threadIdx.x;
    if (i >= n) return;
    float v = src[i];
    __nv_bfloat16 h = __float2bfloat16(v);
    oh[i] = h;
    ol[i] = __float2bfloat16(v - __bfloat162float(h));
}
__global__ void k_wt_all(const float* __restrict__ Wemb, const float* __restrict__ gatW,
                         const float* __restrict__ ffW1, const float* __restrict__ ffW2,
                         const float* __restrict__ decW1) {
    int job = blockIdx.y;
    const float* W;
    __nv_bfloat16 *th, *tl;
    int K, N, Kpad, Npad;
    if (job == 0)      { W = Wemb;                 K = IND;  N = DD;  Kpad = IND;  Npad = DD;
                         th = gb_WembT_h;          tl = gb_WembT_l; }
    else if (job <= 3) { int l = job - 1;  W = gatW + l * DD * DD;   K = DD;  N = DD;  Kpad = DD;  Npad = DD;
                         th = gb_gatWT_h + l * DD * DD;  tl = gb_gatWT_l + l * DD * DD; }
    else if (job <= 6) { int l = job - 4;  W = ffW1 + l * DD * FFD;  K = DD;  N = FFD; Kpad = DD;  Npad = FFP;
                         th = gb_W1T_h + l * FFP * DD;   tl = gb_W1T_l + l * FFP * DD; }
    else if (job <= 9) { int l = job - 7;  W = ffW2 + l * FFD * DD;  K = FFD; N = DD;  Kpad = FFP; Npad = DD;
                         th = gb_W2T_h + l * DD * FFP;   tl = gb_W2T_l + l * DD * FFP; }
    else               { W = decW1;                K = CATD; N = DD; Kpad = CATD; Npad = DD;
                         th = gb_dW1T_h;           tl = gb_dW1T_l; }
    int total = Npad * Kpad;
    for (int i = blockIdx.x * 256 + threadIdx.x; i < total; i += gridDim.x * 256) {
        int n = i / Kpad, k = i % Kpad;
        float v = (k < K && n < N) ? W[(size_t)k * N + n] : 0.f;
        __nv_bfloat16 h = __float2bfloat16(v);
        th[i] = h;
        tl[i] = __float2bfloat16(v - __bfloat162float(h));
    }
}

// ---------------- tensor-core GEMM (bf16 3-term, 128x64 tiles, cp.async 2-stage) ----------------
__device__ __forceinline__ void mma16816(float* c, const uint32_t* a, uint32_t b0, uint32_t b1) {
    asm volatile(
        "mma.sync.aligned.m16n8k16.row.col.f32.bf16.bf16.f32 "
        "{%0,%1,%2,%3}, {%4,%5,%6,%7}, {%8,%9}, {%0,%1,%2,%3};"
        : "+f"(c[0]), "+f"(c[1]), "+f"(c[2]), "+f"(c[3])
        : "r"(a[0]), "r"(a[1]), "r"(a[2]), "r"(a[3]), "r"(b0), "r"(b1));
}
__device__ __forceinline__ void ldmx4(uint32_t* r, uint32_t addr) {
    asm volatile("ldmatrix.sync.aligned.m8n8.x4.shared.b16 {%0,%1,%2,%3}, [%4];"
                 : "=r"(r[0]), "=r"(r[1]), "=r"(r[2]), "=r"(r[3]) : "r"(addr));
}
__device__ __forceinline__ void cpa16(uint32_t dst, const void* src, bool valid) {
    int sz = valid ? 16 : 0;
    asm volatile("cp.async.cg.shared.global [%0], [%1], 16, %2;"
                 :: "r"(dst), "l"(src), "r"(sz) : "memory");
}
#define CP_COMMIT() asm volatile("cp.async.commit_group;" ::: "memory")
#define CP_WAIT(n)  asm volatile("cp.async.wait_group %0;" :: "n"(n) : "memory")

#define SA 40
#define BUF_A 10240
#define BUF_Bb 5120
#define STAGE_B (2 * BUF_A + 2 * BUF_Bb)   // 30720
#define SMEM_REQ (2 * STAGE_B)             // 61440
#define OFF_AL BUF_A
#define OFF_BH (2 * BUF_A)
#define OFF_BL (2 * BUF_A + BUF_Bb)

__global__ __launch_bounds__(256, 3) void tgemm(
    const __nv_bfloat16* __restrict__ Ahi, const __nv_bfloat16* __restrict__ Alo, int lda,
    const __nv_bfloat16* __restrict__ Bhi, const __nv_bfloat16* __restrict__ Blo, int ldb,
    int nrows, int K, int N, int nbrows,
    float* __restrict__ C, int ldc,
    const float* __restrict__ bias, int biasN,
    const float* __restrict__ addsrc, int ldadd,
    int do_relu,
    __nv_bfloat16* __restrict__ Ohi, __nv_bfloat16* __restrict__ Olo, int ldo,
    const float* __restrict__ attnl, const float* __restrict__ attnr,
    float* __restrict__ elout, float* __restrict__ erout)
{
    extern __shared__ __align__(16) char smem_raw[];
    uint32_t sm0 = (uint32_t)__cvta_generic_to_shared(smem_raw);

    const int tid = threadIdx.x;
    const int wid = tid >> 5, lane = tid & 31;
    const int gid = lane >> 2, tig = lane & 3;
    const int wm = wid & 3, wn = wid >> 2;
    const int row0 = blockIdx.y * 128, col0 = blockIdx.x * 64;

    const int fr  = tid >> 2;
    const int fseg = tid & 3;
    const uint32_t fdst0 = (uint32_t)((fr * SA + fseg * 8) * 2);
    const uint32_t fdst1 = (uint32_t)(((fr + 64) * SA + fseg * 8) * 2);

    const uint32_t aoffE = (uint32_t)((wm * 32 + (lane & 15)) * SA + ((lane >> 4) << 3));
    const uint32_t boffE = (uint32_t)((wn * 32 + ((lane >> 4) << 3) + (lane & 7)) * SA
                                      + (((lane >> 3) & 1) << 3));

    float acc[2][4][4];
    #pragma unroll
    for (int mt = 0; mt < 2; mt++)
        #pragma unroll
        for (int nt = 0; nt < 4; nt++)
            #pragma unroll
            for (int j = 0; j < 4; j++) acc[mt][nt][j] = 0.f;

    const int nch = K >> 5;

    {
        uint32_t sb = sm0;
        int gr0 = row0 + fr, gr1 = row0 + fr + 64;
        int gn0 = col0 + fr;
        bool va0 = gr0 < nrows, va1 = gr1 < nrows;
        bool vb0 = gn0 < nbrows;
        int gk = fseg * 8;
        size_t a0 = (size_t)(va0 ? gr0 : row0) * lda + gk;
        size_t a1 = (size_t)(va1 ? gr1 : row0) * lda + gk;
        size_t b0 = (size_t)(vb0 ? gn0 : col0) * ldb + gk;
        cpa16(sb + fdst0,          Ahi + a0, va0);
        cpa16(sb + fdst1,          Ahi + a1, va1);
        cpa16(sb + OFF_AL + fdst0, Alo + a0, va0);
        cpa16(sb + OFF_AL + fdst1, Alo + a1, va1);
        cpa16(sb + OFF_BH + fdst0, Bhi + b0, vb0);
        cpa16(sb + OFF_BL + fdst0, Blo + b0, vb0);
        CP_COMMIT();
    }

    for (int ch = 0; ch < nch; ch++) {
        const uint32_t sb = sm0 + (uint32_t)(ch & 1) * STAGE_B;
        if (ch + 1 < nch) {
            const int k0 = (ch + 1) << 5;
            uint32_t nb = sm0 + (uint32_t)((ch + 1) & 1) * STAGE_B;
            int gr0 = row0 + fr, gr1 = row0 + fr + 64;
            int gn0 = col0 + fr;
            bool va0 = gr0 < nrows, va1 = gr1 < nrows;
            bool vb0 = gn0 < nbrows;
            int gk = k0 + fseg * 8;
            size_t a0 = (size_t)(va0 ? gr0 : row0) * lda + gk;
            size_t a1 = (size_t)(va1 ? gr1 : row0) * lda + gk;
            size_t b0 = (size_t)(vb0 ? gn0 : col0) * ldb + gk;
            cpa16(nb + fdst0,          Ahi + a0, va0);
            cpa16(nb + fdst1,          Ahi + a1, va1);
            cpa16(nb + OFF_AL + fdst0, Alo + a0, va0);
            cpa16(nb + OFF_AL + fdst1, Alo + a1, va1);
            cpa16(nb + OFF_BH + fdst0, Bhi + b0, vb0);
            cpa16(nb + OFF_BL + fdst0, Blo + b0, vb0);
            CP_COMMIT();
            CP_WAIT(1);
        } else {
            CP_WAIT(0);
        }
        __syncthreads();

        const uint32_t uAh = sb, uAl = sb + OFF_AL, uBh = sb + OFF_BH, uBl = sb + OFF_BL;
        #pragma unroll
        for (int ks = 0; ks < 32; ks += 16) {
            uint32_t aH[2][4], aL[2][4];
            #pragma unroll
            for (int mt = 0; mt < 2; mt++) {
                uint32_t ao = (aoffE + (uint32_t)(mt * 16 * SA + ks)) * 2u;
                ldmx4(aH[mt], uAh + ao);
                ldmx4(aL[mt], uAl + ao);
            }
            #pragma unroll
            for (int nt2 = 0; nt2 < 2; nt2++) {
                uint32_t bo = (boffE + (uint32_t)(nt2 * 16 * SA + ks)) * 2u;
                uint32_t bh[4], bl[4];
                ldmx4(bh, uBh + bo);
                ldmx4(bl, uBl + bo);
                #pragma unroll
                for (int sub = 0; sub < 2; sub++) {
                    int nt = nt2 * 2 + sub;
                    uint32_t b0h = bh[sub * 2], b1h = bh[sub * 2 + 1];
                    uint32_t b0l = bl[sub * 2], b1l = bl[sub * 2 + 1];
                    #pragma unroll
                    for (int mt = 0; mt < 2; mt++) {
                        mma16816(acc[mt][nt], aH[mt], b0h, b1h);
                        mma16816(acc[mt][nt], aL[mt], b0h, b1h);
                        mma16816(acc[mt][nt], aH[mt], b0l, b1l);
                    }
                }
            }
        }
        __syncthreads();
    }

    // ---- optional fused el/er reduction scratch (reuses pipeline smem) ----
    float* s_red = (float*)smem_raw;   // [0,512)=el, [512,1024)=er ; 4 heads per CTA
    const bool doattn = (attnl != nullptr);
    if (doattn) {
        #pragma unroll
        for (int i = 0; i < 4; i++) s_red[tid + i * 256] = 0.f;
        __syncthreads();
    }

    // ---- fused epilogue ----
    #pragma unroll
    for (int mt = 0; mt < 2; mt++) {
        #pragma unroll
        for (int nt = 0; nt < 4; nt++) {
            int gc = col0 + wn * 32 + nt * 8 + tig * 2;
            if (gc >= N) continue;
            float al0 = 0.f, al1 = 0.f, ar0 = 0.f, ar1 = 0.f;
            if (doattn) {
                al0 = attnl[gc]; al1 = attnl[gc + 1];
                ar0 = attnr[gc]; ar1 = attnr[gc + 1];
            }
            int hh = (gc >> 4) & 3;
            #pragma unroll
            for (int half = 0; half < 2; half++) {
                int gr = row0 + wm * 32 + mt * 16 + gid + half * 8;
                if (gr >= nrows) continue;
                float v0 = acc[mt][nt][half * 2 + 0];
                float v1 = acc[mt][nt][half * 2 + 1];
                if (bias) {
                    v0 += (gc < biasN) ? bias[gc] : 0.f;
                    v1 += (gc + 1 < biasN) ? bias[gc + 1] : 0.f;
                }
                if (addsrc) {
                    v0 += addsrc[(size_t)gr * ldadd + gc];
                    v1 += addsrc[(size_t)gr * ldadd + gc + 1];
                }
                if (do_relu) { v0 = fmaxf(v0, 0.f); v1 = fmaxf(v1, 0.f); }
                if (C) *(float2*)&C[(size_t)gr * ldc + gc] = make_float2(v0, v1);
                if (Ohi) {
                    __nv_bfloat16 h0 = __float2bfloat16(v0);
                    __nv_bfloat16 h1 = __float2bfloat16(v1);
                    __nv_bfloat162 hp; hp.x = h0; hp.y = h1;
                    __nv_bfloat162 lp;
                    lp.x = __float2bfloat16(v0 - __bfloat162float(h0));
                    lp.y = __float2bfloat16(v1 - __bfloat162float(h1));
                    *(__nv_bfloat162*)&Ohi[(size_t)gr * ldo + gc] = hp;
                    *(__nv_bfloat162*)&Olo[(size_t)gr * ldo + gc] = lp;
                }
                if (doattn) {
                    int rr = gr - row0;
                    atomicAdd(&s_red[rr * 4 + hh],       fmaf(v0, al0, v1 * al1));
                    atomicAdd(&s_red[512 + rr * 4 + hh], fmaf(v0, ar0, v1 * ar1));
                }
            }
        }
    }

    if (doattn) {
        __syncthreads();
        for (int t = tid; t < 512; t += 256) {
            int r = t >> 2, hh = t & 3;
            int gr = row0 + r;
            if (gr < nrows) {
                int head = (col0 >> 4) + hh;
                elout[(size_t)gr * HH + head] = s_red[r * 4 + hh];
                erout[(size_t)gr * HH + head] = s_red[512 + r * 4 + hh];
            }
        }
    }
}

// ---------------- GAT aggregation ----------------
__global__ __launch_bounds__(256) void k_agg(int layer, const float* __restrict__ bias) {
    int warp = threadIdx.x >> 5;
    int lane = threadIdx.x & 31;
    int n = blockIdx.x * 8 + warp;
    if (n >= NN) return;
    int h = lane >> 2;
    int sub = lane & 3;
    float er_n = g_er[n * HH + h];
    int beg = g_rowptr[n], end = g_rowptr[n + 1];
    float m = -INFINITY, d = 0.f;
    float4 acc = {0.f, 0.f, 0.f, 0.f};
    for (int i = beg; i < end; i++) {
        int s = g_csr_src[i];
        float e = g_el[s * HH + h] + er_n;
        e = (e > 0.f) ? e : NEG_SLOPE * e;
        float4 f = *(const float4*)(&g_feat[s * DD + h * 16 + sub * 4]);
        float mn = fmaxf(m, e);
        float sc = __expf(m - mn);
        float w  = __expf(e - mn);
        d = fmaf(d, sc, w);
        acc.x = fmaf(acc.x, sc, w * f.x);
        acc.y = fmaf(acc.y, sc, w * f.y);
        acc.z = fmaf(acc.z, sc, w * f.z);
        acc.w = fmaf(acc.w, sc, w * f.w);
        m = mn;
    }
    float inv = (d > 0.f) ? (1.f / d) : 0.f;
    int off = h * 16 + sub * 4;
    float4 hv = *(const float4*)(&g_Xcat[(size_t)n * CATD + layer * DD + off]);
    float4 bv = *(const float4*)(&bias[off]);
    float4 o;
    o.x = hv.x + acc.x * inv + bv.x;
    o.y = hv.y + acc.y * inv + bv.y;
    o.z = hv.z + acc.z * inv + bv.z;
    o.w = hv.w + acc.w * inv + bv.w;
    *(float4*)(&g_h1[n * DD + off]) = o;
}

// ---------------- BatchNorm ----------------
__global__ void k_bnstats(const float* __restrict__ src, int ld) {
    int c = threadIdx.x;
    int r0 = blockIdx.x * 256;
    float s = 0.f, q = 0.f;
    for (int r = 0; r < 256; r++) {
        int row = r0 + r;
        if (row >= NN) break;
        float v = src[(size_t)row * ld + c];
        s += v;
        q = fmaf(v, v, q);
    }
    atomicAdd(&g_stats[c], s);
    atomicAdd(&g_stats[128 + c], q);
}
__global__ void k_bncoef(const float* __restrict__ g, const float* __restrict__ b) {
    int c = threadIdx.x;
    if (c >= 128) return;
    float mu = g_stats[c] / (float)NN;
    float var = g_stats[128 + c] / (float)NN - mu * mu;
    float a = g[c] * rsqrtf(var + EPSV);
    g_coef[c] = a;
    g_coef[128 + c] = b[c] - mu * a;
    g_stats[c] = 0.f;
    g_stats[128 + c] = 0.f;
}
__global__ void k_bnapply(const float* __restrict__ src, int lds,
                          float* __restrict__ dst, int ldd,
                          __nv_bfloat16* __restrict__ oh, __nv_bfloat16* __restrict__ ol, int ldo) {
    int t = blockIdx.x * 256 + threadIdx.x;
    if (t >= NN * DD) return;
    int n = t >> 7, c = t & 127;
    float v = fmaf(g_coef[c], src[(size_t)n * lds + c], g_coef[128 + c]);
    dst[(size_t)n * ldd + c] = v;
    __nv_bfloat16 h = __float2bfloat16(v);
    oh[(size_t)n * ldo + c] = h;
    ol[(size_t)n * ldo + c] = __float2bfloat16(v - __bfloat162float(h));
}

// ---------------- decoder tail ----------------
__global__ __launch_bounds__(256) void k_dec(const float* __restrict__ w2,
                                             float* __restrict__ out) {
    int warp = threadIdx.x >> 5;
    int lane = threadIdx.x & 31;
    int n = blockIdx.x * 8 + warp;
    if (n >= NN) return;
    int c0 = lane * 4;
    float4 z4 = *(const float4*)(&g_z[n * DD + c0]);
    float v = 0.f;
    #pragma unroll
    for (int j = 0; j < 4; j++) {
        int c = c0 + j;
        float zz = (j == 0) ? z4.x : (j == 1) ? z4.y : (j == 2) ? z4.z : z4.w;
        float hv = fmaf(g_coef[c], zz, g_coef[128 + c]);
        hv = fmaxf(hv, 0.f);
        v = fmaf(hv, w2[c], v);
    }
    #pragma unroll
    for (int o = 16; o > 0; o >>= 1)
        v += __shfl_down_sync(0xFFFFFFFFu, v, o);
    if (lane == 0) out[n] = v;
}

// ---------------- host orchestration ----------------
static inline int cdiv(int a, int b) { return (a + b - 1) / b; }

extern "C" void kernel_launch(void* const* d_in, const int* in_sizes, int n_in,
                              void* d_out, int out_size) {
    const float* x      = (const float*)d_in[0];
    const int*   src    = (const int*)  d_in[1];
    const int*   dst    = (const int*)  d_in[2];
    const float* W_emb  = (const float*)d_in[3];
    const float* b_emb  = (const float*)d_in[4];
    const float* gat_W  = (const float*)d_in[5];
    const float* attn_l = (const float*)d_in[6];
    const float* attn_r = (const float*)d_in[7];
    const float* gat_b  = (const float*)d_in[8];
    const float* bn1_g  = (const float*)d_in[9];
    const float* bn1_b  = (const float*)d_in[10];
    const float* ff_W1  = (const float*)d_in[11];
    const float* ff_b1  = (const float*)d_in[12];
    const float* ff_W2  = (const float*)d_in[13];
    const float* ff_b2  = (const float*)d_in[14];
    const float* bn2_g  = (const float*)d_in[15];
    const float* bn2_b  = (const float*)d_in[16];
    const float* dec_W1 = (const float*)d_in[17];
    const float* dec_bn_g = (const float*)d_in[18];
    const float* dec_bn_b = (const float*)d_in[19];
    const float* dec_W2 = (const float*)d_in[20];
    float* out = (float*)d_out;

    float *p_xcat, *p_feat, *p_h1, *p_h2, *p_z, *p_el, *p_er;
    cudaGetSymbolAddress((void**)&p_xcat, g_Xcat);
    cudaGetSymbolAddress((void**)&p_feat, g_feat);
    cudaGetSymbolAddress((void**)&p_h1,   g_h1);
    cudaGetSymbolAddress((void**)&p_h2,   g_h2);
    cudaGetSymbolAddress((void**)&p_z,    g_z);
    cudaGetSymbolAddress((void**)&p_el,   g_el);
    cudaGetSymbolAddress((void**)&p_er,   g_er);
    __nv_bfloat16 *xh, *xl, *Xh, *Xl, *hbh, *hbl, *th, *tl;
    __nv_bfloat16 *WembTh, *WembTl, *gatWTh, *gatWTl, *W1Th, *W1Tl, *W2Th, *W2Tl, *dW1Th, *dW1Tl;
    cudaGetSymbolAddress((void**)&xh,  gb_xh);   cudaGetSymbolAddress((void**)&xl,  gb_xl);
    cudaGetSymbolAddress((void**)&Xh,  gb_Xh);   cudaGetSymbolAddress((void**)&Xl,  gb_Xl);
    cudaGetSymbolAddress((void**)&hbh, gb_hbh);  cudaGetSymbolAddress((void**)&hbl, gb_hbl);
    cudaGetSymbolAddress((void**)&th,  gb_th);   cudaGetSymbolAddress((void**)&tl,  gb_tl);
    cudaGetSymbolAddress((void**)&WembTh, gb_WembT_h); cudaGetSymbolAddress((void**)&WembTl, gb_WembT_l);
    cudaGetSymbolAddress((void**)&gatWTh, gb_gatWT_h); cudaGetSymbolAddress((void**)&gatWTl, gb_gatWT_l);
    cudaGetSymbolAddress((void**)&W1Th, gb_W1T_h);     cudaGetSymbolAddress((void**)&W1Tl, gb_W1T_l);
    cudaGetSymbolAddress((void**)&W2Th, gb_W2T_h);     cudaGetSymbolAddress((void**)&W2Tl, gb_W2T_l);
    cudaGetSymbolAddress((void**)&dW1Th, gb_dW1T_h);   cudaGetSymbolAddress((void**)&dW1Tl, gb_dW1T_l);

    cudaFuncSetAttribute(tgemm, cudaFuncAttributeMaxDynamicSharedMemorySize, SMEM_REQ);

    const int egrid = cdiv(EE, 256);
    const int ngrid = cdiv(NN, 256);
    const int mt = cdiv(NN, 128);   // 313 M tiles

    // ---- conversions first, then embed GEMM early (CSR build only needed by k_agg) ----
    k_cvt<<<cdiv(NN * IND, 256), 256>>>(x, xh, xl, NN * IND);
    k_wt_all<<<dim3(112, 11), 256>>>(W_emb, gat_W, ff_W1, ff_W2, dec_W1);
    k_zero_deg<<<ngrid, 256>>>();

    tgemm<<<dim3(2, mt), 256, SMEM_REQ>>>(xh, xl, IND, WembTh, WembTl, IND,
        NN, IND, DD, DD, p_xcat, CATD, b_emb, DD, nullptr, 0, 0, Xh, Xl, CATD,
        nullptr, nullptr, nullptr, nullptr);

    // ---- CSR build ----
    k_hist<<<egrid, 256>>>(dst);
    k_scan<<<1, 1024>>>();
    k_scatter<<<egrid, 256>>>(src, dst);

    for (int l = 0; l < LL; l++) {
        // feat = h @ gat_W[l]  (+fused el/er)
        tgemm<<<dim3(2, mt), 256, SMEM_REQ>>>(Xh + l * DD, Xl + l * DD, CATD,
            gatWTh + l * DD * DD, gatWTl + l * DD * DD, DD,
            NN, DD, DD, DD, p_feat, DD, nullptr, 0, nullptr, 0, 0, nullptr, nullptr, 0,
            attn_l + l * DD, attn_r + l * DD, p_el, p_er);
        k_agg<<<cdiv(NN, 8), 256>>>(l, gat_b + l * DD);
        // BN1 -> hb
        k_bnstats<<<cdiv(NN, 256), 128>>>(p_h1, DD);
        k_bncoef<<<1, 128>>>(bn1_g + l * DD, bn1_b + l * DD);
        k_bnapply<<<cdiv(NN * DD, 256), 256>>>(p_h1, DD, p_feat, DD, hbh, hbl, DD);
        // t = relu(hb @ W1 + b1)
        tgemm<<<dim3(4, mt), 256, SMEM_REQ>>>(hbh, hbl, DD,
            W1Th + l * FFP * DD, W1Tl + l * FFP * DD, DD,
            NN, DD, FFP, FFP, nullptr, 0, ff_b1 + l * FFD, FFD, nullptr, 0, 1, th, tl, FFP,
            nullptr, nullptr, nullptr, nullptr);
        // h2 = t @ W2 + b2 + hb
        tgemm<<<dim3(2, mt), 256, SMEM_REQ>>>(th, tl, FFP,
            W2Th + l * DD * FFP, W2Tl + l * DD * FFP, FFP,
            NN, FFP, DD, DD, p_h2, DD, ff_b2 + l * DD, DD, p_feat, DD, 0, nullptr, nullptr, 0,
            nullptr, nullptr, nullptr, nullptr);
        // BN2 -> Xcat slice l+1
        k_bnstats<<<cdiv(NN, 256), 128>>>(p_h2, DD);
        k_bncoef<<<1, 128>>>(bn2_g + l * DD, bn2_b + l * DD);
        k_bnapply<<<cdiv(NN * DD, 256), 256>>>(p_h2, DD, p_xcat + (l + 1) * DD, CATD,
                                               Xh + (l + 1) * DD, Xl + (l + 1) * DD, CATD);
    }

    // ---- decoder ----
    tgemm<<<dim3(2, mt), 256, SMEM_REQ>>>(Xh, Xl, CATD, dW1Th, dW1Tl, CATD,
        NN, CATD, DD, DD, p_z, DD, nullptr, 0, nullptr, 0, 0, nullptr, nullptr, 0,
        nullptr, nullptr, nullptr, nullptr);
    k_bnstats<<<cdiv(NN, 256), 128>>>(p_z, DD);
    k_bncoef<<<1, 128>>>(dec_bn_g, dec_bn_b);
    k_dec<<<cdiv(NN, 8), 256>>>(dec_W2, out);
}

// round 15
// speedup vs baseline: 1.0171x; 1.0171x over previous
#include <cuda_runtime.h>
#include <cuda_bf16.h>
#include <math.h>
#include <stdint.h>

#define NN   40000
#define EE   640000
#define DD   128
#define HH   8
#define LL   3
#define IND  64
#define FFD  218
#define FFP  224
#define CATD 512
#define EPSV 1e-5f
#define NEG_SLOPE 0.2f

// ---------------- device scratch ----------------
__device__ __align__(256) float g_Xcat[NN * CATD];
__device__ __align__(256) float g_feat[NN * DD];
__device__ __align__(256) float g_el[NN * HH];
__device__ __align__(256) float g_er[NN * HH];
__device__ __align__(256) float g_h1[NN * DD];
__device__ __align__(256) float g_h2[NN * DD];
__device__ __align__(256) float g_z [NN * DD];
__device__ __align__(256) float g_stats[256];   // zero-init; k_bncoef re-zeroes after use
__device__ __align__(256) float g_coef[256];
__device__ int g_deg[NN];
__device__ int g_rowptr[NN + 1];
__device__ int g_wp[NN];
__device__ int g_csr_src[EE];

// bf16 hi/lo operand buffers
__device__ __align__(256) __nv_bfloat16 gb_xh[NN * IND],   gb_xl[NN * IND];
__device__ __align__(256) __nv_bfloat16 gb_Xh[NN * CATD],  gb_Xl[NN * CATD];
__device__ __align__(256) __nv_bfloat16 gb_hbh[NN * DD],   gb_hbl[NN * DD];
__device__ __align__(256) __nv_bfloat16 gb_th[NN * FFP],   gb_tl[NN * FFP];
__device__ __align__(256) __nv_bfloat16 gb_WembT_h[DD * IND],     gb_WembT_l[DD * IND];
__device__ __align__(256) __nv_bfloat16 gb_gatWT_h[LL * DD * DD], gb_gatWT_l[LL * DD * DD];
__device__ __align__(256) __nv_bfloat16 gb_W1T_h[LL * FFP * DD],  gb_W1T_l[LL * FFP * DD];
__device__ __align__(256) __nv_bfloat16 gb_W2T_h[LL * DD * FFP],  gb_W2T_l[LL * DD * FFP];
__device__ __align__(256) __nv_bfloat16 gb_dW1T_h[DD * CATD],     gb_dW1T_l[DD * CATD];

// ---------------- CSR build ----------------
__global__ void k_zero_deg() {
    int i = blockIdx.x * 256 + threadIdx.x;
    if (i < NN) g_deg[i] = 0;
}
__global__ void k_hist(const int* __restrict__ dst) {
    int e = blockIdx.x * 256 + threadIdx.x;
    if (e < EE) atomicAdd(&g_deg[dst[e]], 1);
}
__global__ void k_scan() {
    __shared__ int sm[1024];
    const int tid = threadIdx.x;
    const int C = (NN + 1023) / 1024;   // 40
    const int base = tid * C;
    int s = 0;
    for (int j = 0; j < C; j++) {
        int i = base + j;
        if (i < NN) s += g_deg[i];
    }
    sm[tid] = s;
    __syncthreads();
    for (int off = 1; off < 1024; off <<= 1) {
        int v = (tid >= off) ? sm[tid - off] : 0;
        __syncthreads();
        sm[tid] += v;
        __syncthreads();
    }
    int run = sm[tid] - s;
    for (int j = 0; j < C; j++) {
        int i = base + j;
        if (i < NN) {
            g_rowptr[i] = run;
            g_wp[i] = run;
            run += g_deg[i];
        }
    }
    if (tid == 0) g_rowptr[NN] = EE;
}
__global__ void k_scatter(const int* __restrict__ src, const int* __restrict__ dst) {
    int e = blockIdx.x * 256 + threadIdx.x;
    if (e < EE) {
        int p = atomicAdd(&g_wp[dst[e]], 1);
        g_csr_src[p] = src[e];
    }
}

// ---------------- conversions ----------------
__global__ void k_cvt(const float* __restrict__ src, __nv_bfloat16* __restrict__ oh,
                      __nv_bfloat16* __restrict__ ol, int n) {
    int i = blockIdx.x * 256 + threadIdx.x;
    if (i >= n) return;
    float v = src[i];
    __nv_bfloat16 h = __float2bfloat16(v);
    oh[i] = h;
    ol[i] = __float2bfloat16(v - __bfloat162float(h));
}
__global__ void k_wt_all(const float* __restrict__ Wemb, const float* __restrict__ gatW,
                         const float* __restrict__ ffW1, const float* __restrict__ ffW2,
                         const float* __restrict__ decW1) {
    int job = blockIdx.y;
    const float* W;
    __nv_bfloat16 *th, *tl;
    int K, N, Kpad, Npad;
    if (job == 0)      { W = Wemb;                 K = IND;  N = DD;  Kpad = IND;  Npad = DD;
                         th = gb_WembT_h;          tl = gb_WembT_l; }
    else if (job <= 3) { int l = job - 1;  W = gatW + l * DD * DD;   K = DD;  N = DD;  Kpad = DD;  Npad = DD;
                         th = gb_gatWT_h + l * DD * DD;  tl = gb_gatWT_l + l * DD * DD; }
    else if (job <= 6) { int l = job - 4;  W = ffW1 + l * DD * FFD;  K = DD;  N = FFD; Kpad = DD;  Npad = FFP;
                         th = gb_W1T_h + l * FFP * DD;   tl = gb_W1T_l + l * FFP * DD; }
    else if (job <= 9) { int l = job - 7;  W = ffW2 + l * FFD * DD;  K = FFD; N = DD;  Kpad = FFP; Npad = DD;
                         th = gb_W2T_h + l * DD * FFP;   tl = gb_W2T_l + l * DD * FFP; }
    else               { W = decW1;                K = CATD; N = DD; Kpad = CATD; Npad = DD;
                         th = gb_dW1T_h;           tl = gb_dW1T_l; }
    int total = Npad * Kpad;
    for (int i = blockIdx.x * 256 + threadIdx.x; i < total; i += gridDim.x * 256) {
        int n = i / Kpad, k = i % Kpad;
        float v = (k < K && n < N) ? W[(size_t)k * N + n] : 0.f;
        __nv_bfloat16 h = __float2bfloat16(v);
        th[i] = h;
        tl[i] = __float2bfloat16(v - __bfloat162float(h));
    }
}

// ---------------- tensor-core GEMM (bf16 3-term, 128x64 tiles, cp.async, 1 barrier/chunk) ----------------
__device__ __forceinline__ void mma16816(float* c, const uint32_t* a, uint32_t b0, uint32_t b1) {
    asm volatile(
        "mma.sync.aligned.m16n8k16.row.col.f32.bf16.bf16.f32 "
        "{%0,%1,%2,%3}, {%4,%5,%6,%7}, {%8,%9}, {%0,%1,%2,%3};"
        : "+f"(c[0]), "+f"(c[1]), "+f"(c[2]), "+f"(c[3])
        : "r"(a[0]), "r"(a[1]), "r"(a[2]), "r"(a[3]), "r"(b0), "r"(b1));
}
__device__ __forceinline__ void ldmx4(uint32_t* r, uint32_t addr) {
    asm volatile("ldmatrix.sync.aligned.m8n8.x4.shared.b16 {%0,%1,%2,%3}, [%4];"
                 : "=r"(r[0]), "=r"(r[1]), "=r"(r[2]), "=r"(r[3]) : "r"(addr));
}
__device__ __forceinline__ void cpa16(uint32_t dst, const void* src, bool valid) {
    int sz = valid ? 16 : 0;
    asm volatile("cp.async.cg.shared.global [%0], [%1], 16, %2;"
                 :: "r"(dst), "l"(src), "r"(sz) : "memory");
}
#define CP_COMMIT() asm volatile("cp.async.commit_group;" ::: "memory")
#define CP_WAIT(n)  asm volatile("cp.async.wait_group %0;" :: "n"(n) : "memory")

#define SA 40
#define BUF_A 10240
#define BUF_Bb 5120
#define STAGE_B (2 * BUF_A + 2 * BUF_Bb)   // 30720
#define SMEM_REQ (2 * STAGE_B)             // 61440
#define OFF_AL BUF_A
#define OFF_BH (2 * BUF_A)
#define OFF_BL (2 * BUF_A + BUF_Bb)

__global__ __launch_bounds__(256, 3) void tgemm(
    const __nv_bfloat16* __restrict__ Ahi, const __nv_bfloat16* __restrict__ Alo, int lda,
    const __nv_bfloat16* __restrict__ Bhi, const __nv_bfloat16* __restrict__ Blo, int ldb,
    int nrows, int K, int N, int nbrows,
    float* __restrict__ C, int ldc,
    const float* __restrict__ bias, int biasN,
    const float* __restrict__ addsrc, int ldadd,
    int do_relu,
    __nv_bfloat16* __restrict__ Ohi, __nv_bfloat16* __restrict__ Olo, int ldo)
{
    extern __shared__ __align__(16) char smem_raw[];
    uint32_t sm0 = (uint32_t)__cvta_generic_to_shared(smem_raw);

    const int tid = threadIdx.x;
    const int wid = tid >> 5, lane = tid & 31;
    const int gid = lane >> 2, tig = lane & 3;
    const int wm = wid & 3, wn = wid >> 2;
    const int row0 = blockIdx.y * 128, col0 = blockIdx.x * 64;

    const int fr  = tid >> 2;
    const int fseg = tid & 3;
    const uint32_t fdst0 = (uint32_t)((fr * SA + fseg * 8) * 2);
    const uint32_t fdst1 = (uint32_t)(((fr + 64) * SA + fseg * 8) * 2);

    // chunk-invariant fill pointers + validity (advance by 32 halfs per chunk)
    const int gr0 = row0 + fr, gr1 = row0 + fr + 64;
    const int gn0 = col0 + fr;
    const bool va0 = gr0 < nrows, va1 = gr1 < nrows;
    const bool vb0 = gn0 < nbrows;
    const int gk0 = fseg * 8;
    const __nv_bfloat16* pAh0 = Ahi + (size_t)(va0 ? gr0 : row0) * lda + gk0;
    const __nv_bfloat16* pAh1 = Ahi + (size_t)(va1 ? gr1 : row0) * lda + gk0;
    const __nv_bfloat16* pAl0 = Alo + (size_t)(va0 ? gr0 : row0) * lda + gk0;
    const __nv_bfloat16* pAl1 = Alo + (size_t)(va1 ? gr1 : row0) * lda + gk0;
    const __nv_bfloat16* pBh0 = Bhi + (size_t)(vb0 ? gn0 : col0) * ldb + gk0;
    const __nv_bfloat16* pBl0 = Blo + (size_t)(vb0 ? gn0 : col0) * ldb + gk0;

    const uint32_t aoffE = (uint32_t)((wm * 32 + (lane & 15)) * SA + ((lane >> 4) << 3));
    const uint32_t boffE = (uint32_t)((wn * 32 + ((lane >> 4) << 3) + (lane & 7)) * SA
                                      + (((lane >> 3) & 1) << 3));

    float acc[2][4][4];
    #pragma unroll
    for (int mt = 0; mt < 2; mt++)
        #pragma unroll
        for (int nt = 0; nt < 4; nt++)
            #pragma unroll
            for (int j = 0; j < 4; j++) acc[mt][nt][j] = 0.f;

    const int nch = K >> 5;

    // ---------- prologue: fill stage 0 (chunk 0) ----------
    {
        uint32_t sb = sm0;
        cpa16(sb + fdst0,          pAh0, va0);
        cpa16(sb + fdst1,          pAh1, va1);
        cpa16(sb + OFF_AL + fdst0, pAl0, va0);
        cpa16(sb + OFF_AL + fdst1, pAl1, va1);
        cpa16(sb + OFF_BH + fdst0, pBh0, vb0);
        cpa16(sb + OFF_BL + fdst0, pBl0, vb0);
        CP_COMMIT();
        pAh0 += 32; pAh1 += 32; pAl0 += 32; pAl1 += 32; pBh0 += 32; pBl0 += 32;
    }

    for (int ch = 0; ch < nch; ch++) {
        CP_WAIT(0);          // fill(ch) complete (overlapped compute(ch-1))
        __syncthreads();     // all warps past compute(ch-1) -> stage (ch+1)&1 free
        if (ch + 1 < nch) {
            uint32_t nb = sm0 + (uint32_t)((ch + 1) & 1) * STAGE_B;
            cpa16(nb + fdst0,          pAh0, va0);
            cpa16(nb + fdst1,          pAh1, va1);
            cpa16(nb + OFF_AL + fdst0, pAl0, va0);
            cpa16(nb + OFF_AL + fdst1, pAl1, va1);
            cpa16(nb + OFF_BH + fdst0, pBh0, vb0);
            cpa16(nb + OFF_BL + fdst0, pBl0, vb0);
            CP_COMMIT();
            pAh0 += 32; pAh1 += 32; pAl0 += 32; pAl1 += 32; pBh0 += 32; pBl0 += 32;
        }

        // ---------- compute current stage ----------
        const uint32_t sb = sm0 + (uint32_t)(ch & 1) * STAGE_B;
        const uint32_t uAh = sb, uAl = sb + OFF_AL, uBh = sb + OFF_BH, uBl = sb + OFF_BL;
        #pragma unroll
        for (int ks = 0; ks < 32; ks += 16) {
            uint32_t aH[2][4], aL[2][4];
            #pragma unroll
            for (int mt = 0; mt < 2; mt++) {
                uint32_t ao = (aoffE + (uint32_t)(mt * 16 * SA + ks)) * 2u;
                ldmx4(aH[mt], uAh + ao);
                ldmx4(aL[mt], uAl + ao);
            }
            #pragma unroll
            for (int nt2 = 0; nt2 < 2; nt2++) {
                uint32_t bo = (boffE + (uint32_t)(nt2 * 16 * SA + ks)) * 2u;
                uint32_t bh[4], bl[4];
                ldmx4(bh, uBh + bo);
                ldmx4(bl, uBl + bo);
                #pragma unroll
                for (int sub = 0; sub < 2; sub++) {
                    int nt = nt2 * 2 + sub;
                    uint32_t b0h = bh[sub * 2], b1h = bh[sub * 2 + 1];
                    uint32_t b0l = bl[sub * 2], b1l = bl[sub * 2 + 1];
                    #pragma unroll
                    for (int mt = 0; mt < 2; mt++) {
                        mma16816(acc[mt][nt], aH[mt], b0h, b1h);
                        mma16816(acc[mt][nt], aL[mt], b0h, b1h);
                        mma16816(acc[mt][nt], aH[mt], b0l, b1l);
                    }
                }
            }
        }
    }

    // ---- fused epilogue: bias / skip-add / relu / fp32 store / bf16 hi-lo emit ----
    #pragma unroll
    for (int mt = 0; mt < 2; mt++) {
        #pragma unroll
        for (int nt = 0; nt < 4; nt++) {
            int gc = col0 + wn * 32 + nt * 8 + tig * 2;
            if (gc >= N) continue;
            #pragma unroll
            for (int half = 0; half < 2; half++) {
                int gr = row0 + wm * 32 + mt * 16 + gid + half * 8;
                if (gr >= nrows) continue;
                float v0 = acc[mt][nt][half * 2 + 0];
                float v1 = acc[mt][nt][half * 2 + 1];
                if (bias) {
                    v0 += (gc < biasN) ? bias[gc] : 0.f;
                    v1 += (gc + 1 < biasN) ? bias[gc + 1] : 0.f;
                }
                if (addsrc) {
                    v0 += addsrc[(size_t)gr * ldadd + gc];
                    v1 += addsrc[(size_t)gr * ldadd + gc + 1];
                }
                if (do_relu) { v0 = fmaxf(v0, 0.f); v1 = fmaxf(v1, 0.f); }
                if (C) *(float2*)&C[(size_t)gr * ldc + gc] = make_float2(v0, v1);
                if (Ohi) {
                    __nv_bfloat16 h0 = __float2bfloat16(v0);
                    __nv_bfloat16 h1 = __float2bfloat16(v1);
                    __nv_bfloat162 hp; hp.x = h0; hp.y = h1;
                    __nv_bfloat162 lp;
                    lp.x = __float2bfloat16(v0 - __bfloat162float(h0));
                    lp.y = __float2bfloat16(v1 - __bfloat162float(h1));
                    *(__nv_bfloat162*)&Ohi[(size_t)gr * ldo + gc] = hp;
                    *(__nv_bfloat162*)&Olo[(size_t)gr * ldo + gc] = lp;
                }
            }
        }
    }
}

// ---------------- el/er attention projections ----------------
__global__ void k_eler(const float* __restrict__ al, const float* __restrict__ ar) {
    int t = blockIdx.x * 256 + threadIdx.x;
    if (t >= NN * HH) return;
    int n = t >> 3, h = t & 7;
    const float* f = &g_feat[n * DD + h * 16];
    float sl = 0.f, sr = 0.f;
    #pragma unroll
    for (int i = 0; i < 16; i++) {
        float fv = f[i];
        sl = fmaf(fv, al[h * 16 + i], sl);
        sr = fmaf(fv, ar[h * 16 + i], sr);
    }
    g_el[t] = sl;
    g_er[t] = sr;
}

// ---------------- GAT aggregation ----------------
__global__ __launch_bounds__(256) void k_agg(int layer, const float* __restrict__ bias) {
    int warp = threadIdx.x >> 5;
    int lane = threadIdx.x & 31;
    int n = blockIdx.x * 8 + warp;
    if (n >= NN) return;
    int h = lane >> 2;
    int sub = lane & 3;
    float er_n = g_er[n * HH + h];
    int beg = g_rowptr[n], end = g_rowptr[n + 1];
    float m = -INFINITY, d = 0.f;
    float4 acc = {0.f, 0.f, 0.f, 0.f};
    for (int i = beg; i < end; i++) {
        int s = g_csr_src[i];
        float e = g_el[s * HH + h] + er_n;
        e = (e > 0.f) ? e : NEG_SLOPE * e;
        float4 f = *(const float4*)(&g_feat[s * DD + h * 16 + sub * 4]);
        float mn = fmaxf(m, e);
        float sc = __expf(m - mn);
        float w  = __expf(e - mn);
        d = fmaf(d, sc, w);
        acc.x = fmaf(acc.x, sc, w * f.x);
        acc.y = fmaf(acc.y, sc, w * f.y);
        acc.z = fmaf(acc.z, sc, w * f.z);
        acc.w = fmaf(acc.w, sc, w * f.w);
        m = mn;
    }
    float inv = (d > 0.f) ? (1.f / d) : 0.f;
    int off = h * 16 + sub * 4;
    float4 hv = *(const float4*)(&g_Xcat[(size_t)n * CATD + layer * DD + off]);
    float4 bv = *(const float4*)(&bias[off]);
    float4 o;
    o.x = hv.x + acc.x * inv + bv.x;
    o.y = hv.y + acc.y * inv + bv.y;
    o.z = hv.z + acc.z * inv + bv.z;
    o.w = hv.w + acc.w * inv + bv.w;
    *(float4*)(&g_h1[n * DD + off]) = o;
}

// ---------------- BatchNorm ----------------
__global__ void k_bnstats(const float* __restrict__ src, int ld) {
    int c = threadIdx.x;
    int r0 = blockIdx.x * 256;
    float s = 0.f, q = 0.f;
    for (int r = 0; r < 256; r++) {
        int row = r0 + r;
        if (row >= NN) break;
        float v = src[(size_t)row * ld + c];
        s += v;
        q = fmaf(v, v, q);
    }
    atomicAdd(&g_stats[c], s);
    atomicAdd(&g_stats[128 + c], q);
}
__global__ void k_bncoef(const float* __restrict__ g, const float* __restrict__ b) {
    int c = threadIdx.x;
    if (c >= 128) return;
    float mu = g_stats[c] / (float)NN;
    float var = g_stats[128 + c] / (float)NN - mu * mu;
    float a = g[c] * rsqrtf(var + EPSV);
    g_coef[c] = a;
    g_coef[128 + c] = b[c] - mu * a;
    g_stats[c] = 0.f;
    g_stats[128 + c] = 0.f;
}
__global__ void k_bnapply(const float* __restrict__ src, int lds,
                          float* __restrict__ dst, int ldd,
                          __nv_bfloat16* __restrict__ oh, __nv_bfloat16* __restrict__ ol, int ldo) {
    int t = blockIdx.x * 256 + threadIdx.x;
    if (t >= NN * DD) return;
    int n = t >> 7, c = t & 127;
    float v = fmaf(g_coef[c], src[(size_t)n * lds + c], g_coef[128 + c]);
    dst[(size_t)n * ldd + c] = v;
    __nv_bfloat16 h = __float2bfloat16(v);
    oh[(size_t)n * ldo + c] = h;
    ol[(size_t)n * ldo + c] = __float2bfloat16(v - __bfloat162float(h));
}

// ---------------- decoder tail ----------------
__global__ __launch_bounds__(256) void k_dec(const float* __restrict__ w2,
                                             float* __restrict__ out) {
    int warp = threadIdx.x >> 5;
    int lane = threadIdx.x & 31;
    int n = blockIdx.x * 8 + warp;
    if (n >= NN) return;
    int c0 = lane * 4;
    float4 z4 = *(const float4*)(&g_z[n * DD + c0]);
    float v = 0.f;
    #pragma unroll
    for (int j = 0; j < 4; j++) {
        int c = c0 + j;
        float zz = (j == 0) ? z4.x : (j == 1) ? z4.y : (j == 2) ? z4.z : z4.w;
        float hv = fmaf(g_coef[c], zz, g_coef[128 + c]);
        hv = fmaxf(hv, 0.f);
        v = fmaf(hv, w2[c], v);
    }
    #pragma unroll
    for (int o = 16; o > 0; o >>= 1)
        v += __shfl_down_sync(0xFFFFFFFFu, v, o);
    if (lane == 0) out[n] = v;
}

// ---------------- host orchestration ----------------
static inline int cdiv(int a, int b) { return (a + b - 1) / b; }

extern "C" void kernel_launch(void* const* d_in, const int* in_sizes, int n_in,
                              void* d_out, int out_size) {
    const float* x      = (const float*)d_in[0];
    const int*   src    = (const int*)  d_in[1];
    const int*   dst    = (const int*)  d_in[2];
    const float* W_emb  = (const float*)d_in[3];
    const float* b_emb  = (const float*)d_in[4];
    const float* gat_W  = (const float*)d_in[5];
    const float* attn_l = (const float*)d_in[6];
    const float* attn_r = (const float*)d_in[7];
    const float* gat_b  = (const float*)d_in[8];
    const float* bn1_g  = (const float*)d_in[9];
    const float* bn1_b  = (const float*)d_in[10];
    const float* ff_W1  = (const float*)d_in[11];
    const float* ff_b1  = (const float*)d_in[12];
    const float* ff_W2  = (const float*)d_in[13];
    const float* ff_b2  = (const float*)d_in[14];
    const float* bn2_g  = (const float*)d_in[15];
    const float* bn2_b  = (const float*)d_in[16];
    const float* dec_W1 = (const float*)d_in[17];
    const float* dec_bn_g = (const float*)d_in[18];
    const float* dec_bn_b = (const float*)d_in[19];
    const float* dec_W2 = (const float*)d_in[20];
    float* out = (float*)d_out;

    float *p_xcat, *p_feat, *p_h1, *p_h2, *p_z;
    cudaGetSymbolAddress((void**)&p_xcat, g_Xcat);
    cudaGetSymbolAddress((void**)&p_feat, g_feat);
    cudaGetSymbolAddress((void**)&p_h1,   g_h1);
    cudaGetSymbolAddress((void**)&p_h2,   g_h2);
    cudaGetSymbolAddress((void**)&p_z,    g_z);
    __nv_bfloat16 *xh, *xl, *Xh, *Xl, *hbh, *hbl, *th, *tl;
    __nv_bfloat16 *WembTh, *WembTl, *gatWTh, *gatWTl, *W1Th, *W1Tl, *W2Th, *W2Tl, *dW1Th, *dW1Tl;
    cudaGetSymbolAddress((void**)&xh,  gb_xh);   cudaGetSymbolAddress((void**)&xl,  gb_xl);
    cudaGetSymbolAddress((void**)&Xh,  gb_Xh);   cudaGetSymbolAddress((void**)&Xl,  gb_Xl);
    cudaGetSymbolAddress((void**)&hbh, gb_hbh);  cudaGetSymbolAddress((void**)&hbl, gb_hbl);
    cudaGetSymbolAddress((void**)&th,  gb_th);   cudaGetSymbolAddress((void**)&tl,  gb_tl);
    cudaGetSymbolAddress((void**)&WembTh, gb_WembT_h); cudaGetSymbolAddress((void**)&WembTl, gb_WembT_l);
    cudaGetSymbolAddress((void**)&gatWTh, gb_gatWT_h); cudaGetSymbolAddress((void**)&gatWTl, gb_gatWT_l);
    cudaGetSymbolAddress((void**)&W1Th, gb_W1T_h);     cudaGetSymbolAddress((void**)&W1Tl, gb_W1T_l);
    cudaGetSymbolAddress((void**)&W2Th, gb_W2T_h);     cudaGetSymbolAddress((void**)&W2Tl, gb_W2T_l);
    cudaGetSymbolAddress((void**)&dW1Th, gb_dW1T_h);   cudaGetSymbolAddress((void**)&dW1Tl, gb_dW1T_l);

    cudaFuncSetAttribute(tgemm, cudaFuncAttributeMaxDynamicSharedMemorySize, SMEM_REQ);

    const int egrid = cdiv(EE, 256);
    const int ngrid = cdiv(NN, 256);
    const int mt = cdiv(NN, 128);   // 313 M tiles

    // ---- conversions first, then embed GEMM early (CSR build only needed by k_agg) ----
    k_cvt<<<cdiv(NN * IND, 256), 256>>>(x, xh, xl, NN * IND);
    k_wt_all<<<dim3(112, 11), 256>>>(W_emb, gat_W, ff_W1, ff_W2, dec_W1);
    k_zero_deg<<<ngrid, 256>>>();

    tgemm<<<dim3(2, mt), 256, SMEM_REQ>>>(xh, xl, IND, WembTh, WembTl, IND,
        NN, IND, DD, DD, p_xcat, CATD, b_emb, DD, nullptr, 0, 0, Xh, Xl, CATD);

    // ---- CSR build ----
    k_hist<<<egrid, 256>>>(dst);
    k_scan<<<1, 1024>>>();
    k_scatter<<<egrid, 256>>>(src, dst);

    for (int l = 0; l < LL; l++) {
        // feat = h @ gat_W[l]
        tgemm<<<dim3(2, mt), 256, SMEM_REQ>>>(Xh + l * DD, Xl + l * DD, CATD,
            gatWTh + l * DD * DD, gatWTl + l * DD * DD, DD,
            NN, DD, DD, DD, p_feat, DD, nullptr, 0, nullptr, 0, 0, nullptr, nullptr, 0);
        k_eler<<<cdiv(NN * HH, 256), 256>>>(attn_l + l * DD, attn_r + l * DD);
        k_agg<<<cdiv(NN, 8), 256>>>(l, gat_b + l * DD);
        // BN1 -> hb
        k_bnstats<<<cdiv(NN, 256), 128>>>(p_h1, DD);
        k_bncoef<<<1, 128>>>(bn1_g + l * DD, bn1_b + l * DD);
        k_bnapply<<<cdiv(NN * DD, 256), 256>>>(p_h1, DD, p_feat, DD, hbh, hbl, DD);
        // t = relu(hb @ W1 + b1)
        tgemm<<<dim3(4, mt), 256, SMEM_REQ>>>(hbh, hbl, DD,
            W1Th + l * FFP * DD, W1Tl + l * FFP * DD, DD,
            NN, DD, FFP, FFP, nullptr, 0, ff_b1 + l * FFD, FFD, nullptr, 0, 1, th, tl, FFP);
        // h2 = t @ W2 + b2 + hb
        tgemm<<<dim3(2, mt), 256, SMEM_REQ>>>(th, tl, FFP,
            W2Th + l * DD * FFP, W2Tl + l * DD * FFP, FFP,
            NN, FFP, DD, DD, p_h2, DD, ff_b2 + l * DD, DD, p_feat, DD, 0, nullptr, nullptr, 0);
        // BN2 -> Xcat slice l+1
        k_bnstats<<<cdiv(NN, 256), 128>>>(p_h2, DD);
        k_bncoef<<<1, 128>>>(bn2_g + l * DD, bn2_b + l * DD);
        k_bnapply<<<cdiv(NN * DD, 256), 256>>>(p_h2, DD, p_xcat + (l + 1) * DD, CATD,
                                               Xh + (l + 1) * DD, Xl + (l + 1) * DD, CATD);
    }

    // ---- decoder ----
    tgemm<<<dim3(2, mt), 256, SMEM_REQ>>>(Xh, Xl, CATD, dW1Th, dW1Tl, CATD,
        NN, CATD, DD, DD, p_z, DD, nullptr, 0, nullptr, 0, 0, nullptr, nullptr, 0);
    k_bnstats<<<cdiv(NN, 256), 128>>>(p_z, DD);
    k_bncoef<<<1, 128>>>(dec_bn_g, dec_bn_b);
    k_dec<<<cdiv(NN, 8), 256>>>(dec_W2, out);
}

// round 16
// speedup vs baseline: 1.0308x; 1.0135x over previous
#include <cuda_runtime.h>
#include <cuda_bf16.h>
#include <math.h>
#include <stdint.h>

#define NN   40000
#define EE   640000
#define DD   128
#define HH   8
#define LL   3
#define IND  64
#define FFD  218
#define FFP  224
#define CATD 512
#define EPSV 1e-5f
#define NEG_SLOPE 0.2f

// ---------------- device scratch ----------------
__device__ __align__(256) float g_Xcat[NN * CATD];
__device__ __align__(256) float g_feat[NN * DD];
__device__ __align__(256) float g_el[NN * HH];
__device__ __align__(256) float g_er[NN * HH];
__device__ __align__(256) float g_h1[NN * DD];
__device__ __align__(256) float g_h2[NN * DD];
__device__ __align__(256) float g_z [NN * DD];
__device__ __align__(256) float g_stats[256];   // zero-init; k_bncoef re-zeroes after use
__device__ __align__(256) float g_coef[256];
__device__ int g_deg[NN];
__device__ int g_rowptr[NN + 1];
__device__ int g_wp[NN];
__device__ int g_csr_src[EE];

// bf16 hi/lo operand buffers
__device__ __align__(256) __nv_bfloat16 gb_xh[NN * IND],   gb_xl[NN * IND];
__device__ __align__(256) __nv_bfloat16 gb_Xh[NN * CATD],  gb_Xl[NN * CATD];
__device__ __align__(256) __nv_bfloat16 gb_hbh[NN * DD],   gb_hbl[NN * DD];
__device__ __align__(256) __nv_bfloat16 gb_th[NN * FFP],   gb_tl[NN * FFP];
__device__ __align__(256) __nv_bfloat16 gb_WembT_h[DD * IND],     gb_WembT_l[DD * IND];
__device__ __align__(256) __nv_bfloat16 gb_gatWT_h[LL * DD * DD], gb_gatWT_l[LL * DD * DD];
__device__ __align__(256) __nv_bfloat16 gb_W1T_h[LL * FFP * DD],  gb_W1T_l[LL * FFP * DD];
__device__ __align__(256) __nv_bfloat16 gb_W2T_h[LL * DD * FFP],  gb_W2T_l[LL * DD * FFP];
__device__ __align__(256) __nv_bfloat16 gb_dW1T_h[DD * CATD],     gb_dW1T_l[DD * CATD];

// ---------------- CSR build ----------------
__global__ void k_zero_deg() {
    int i = blockIdx.x * 256 + threadIdx.x;
    if (i < NN) g_deg[i] = 0;
}
__global__ void k_hist(const int* __restrict__ dst) {
    int e = blockIdx.x * 256 + threadIdx.x;
    if (e < EE) atomicAdd(&g_deg[dst[e]], 1);
}
__global__ void k_scan() {
    __shared__ int sm[1024];
    const int tid = threadIdx.x;
    const int C = (NN + 1023) / 1024;   // 40
    const int base = tid * C;
    int s = 0;
    for (int j = 0; j < C; j++) {
        int i = base + j;
        if (i < NN) s += g_deg[i];
    }
    sm[tid] = s;
    __syncthreads();
    for (int off = 1; off < 1024; off <<= 1) {
        int v = (tid >= off) ? sm[tid - off] : 0;
        __syncthreads();
        sm[tid] += v;
        __syncthreads();
    }
    int run = sm[tid] - s;
    for (int j = 0; j < C; j++) {
        int i = base + j;
        if (i < NN) {
            g_rowptr[i] = run;
            g_wp[i] = run;
            run += g_deg[i];
        }
    }
    if (tid == 0) g_rowptr[NN] = EE;
}
__global__ void k_scatter(const int* __restrict__ src, const int* __restrict__ dst) {
    int e = blockIdx.x * 256 + threadIdx.x;
    if (e < EE) {
        int p = atomicAdd(&g_wp[dst[e]], 1);
        g_csr_src[p] = src[e];
    }
}

// ---------------- conversions ----------------
__global__ void k_cvt(const float* __restrict__ src, __nv_bfloat16* __restrict__ oh,
                      __nv_bfloat16* __restrict__ ol, int n) {
    int i = blockIdx.x * 256 + threadIdx.x;
    if (i >= n) return;
    float v = src[i];
    __nv_bfloat16 h = __float2bfloat16(v);
    oh[i] = h;
    ol[i] = __float2bfloat16(v - __bfloat162float(h));
}
__global__ void k_wt_all(const float* __restrict__ Wemb, const float* __restrict__ gatW,
                         const float* __restrict__ ffW1, const float* __restrict__ ffW2,
                         const float* __restrict__ decW1) {
    int job = blockIdx.y;
    const float* W;
    __nv_bfloat16 *th, *tl;
    int K, N, Kpad, Npad;
    if (job == 0)      { W = Wemb;                 K = IND;  N = DD;  Kpad = IND;  Npad = DD;
                         th = gb_WembT_h;          tl = gb_WembT_l; }
    else if (job <= 3) { int l = job - 1;  W = gatW + l * DD * DD;   K = DD;  N = DD;  Kpad = DD;  Npad = DD;
                         th = gb_gatWT_h + l * DD * DD;  tl = gb_gatWT_l + l * DD * DD; }
    else if (job <= 6) { int l = job - 4;  W = ffW1 + l * DD * FFD;  K = DD;  N = FFD; Kpad = DD;  Npad = FFP;
                         th = gb_W1T_h + l * FFP * DD;   tl = gb_W1T_l + l * FFP * DD; }
    else if (job <= 9) { int l = job - 7;  W = ffW2 + l * FFD * DD;  K = FFD; N = DD;  Kpad = FFP; Npad = DD;
                         th = gb_W2T_h + l * DD * FFP;   tl = gb_W2T_l + l * DD * FFP; }
    else               { W = decW1;                K = CATD; N = DD; Kpad = CATD; Npad = DD;
                         th = gb_dW1T_h;           tl = gb_dW1T_l; }
    int total = Npad * Kpad;
    for (int i = blockIdx.x * 256 + threadIdx.x; i < total; i += gridDim.x * 256) {
        int n = i / Kpad, k = i % Kpad;
        float v = (k < K && n < N) ? W[(size_t)k * N + n] : 0.f;
        __nv_bfloat16 h = __float2bfloat16(v);
        th[i] = h;
        tl[i] = __float2bfloat16(v - __bfloat162float(h));
    }
}

// ---------------- tensor-core GEMM (bf16 3-term, term-major MMA issue) ----------------
__device__ __forceinline__ void mma16816(float* c, const uint32_t* a, uint32_t b0, uint32_t b1) {
    asm volatile(
        "mma.sync.aligned.m16n8k16.row.col.f32.bf16.bf16.f32 "
        "{%0,%1,%2,%3}, {%4,%5,%6,%7}, {%8,%9}, {%0,%1,%2,%3};"
        : "+f"(c[0]), "+f"(c[1]), "+f"(c[2]), "+f"(c[3])
        : "r"(a[0]), "r"(a[1]), "r"(a[2]), "r"(a[3]), "r"(b0), "r"(b1));
}
__device__ __forceinline__ void ldmx4(uint32_t* r, uint32_t addr) {
    asm volatile("ldmatrix.sync.aligned.m8n8.x4.shared.b16 {%0,%1,%2,%3}, [%4];"
                 : "=r"(r[0]), "=r"(r[1]), "=r"(r[2]), "=r"(r[3]) : "r"(addr));
}
__device__ __forceinline__ void cpa16(uint32_t dst, const void* src, bool valid) {
    int sz = valid ? 16 : 0;
    asm volatile("cp.async.cg.shared.global [%0], [%1], 16, %2;"
                 :: "r"(dst), "l"(src), "r"(sz) : "memory");
}
#define CP_COMMIT() asm volatile("cp.async.commit_group;" ::: "memory")
#define CP_WAIT(n)  asm volatile("cp.async.wait_group %0;" :: "n"(n) : "memory")

#define SA 40
#define BUF_A 10240
#define BUF_Bb 5120
#define STAGE_B (2 * BUF_A + 2 * BUF_Bb)   // 30720
#define SMEM_REQ (2 * STAGE_B)             // 61440
#define OFF_AL BUF_A
#define OFF_BH (2 * BUF_A)
#define OFF_BL (2 * BUF_A + BUF_Bb)

__global__ __launch_bounds__(256, 3) void tgemm(
    const __nv_bfloat16* __restrict__ Ahi, const __nv_bfloat16* __restrict__ Alo, int lda,
    const __nv_bfloat16* __restrict__ Bhi, const __nv_bfloat16* __restrict__ Blo, int ldb,
    int nrows, int K, int N, int nbrows,
    float* __restrict__ C, int ldc,
    const float* __restrict__ bias, int biasN,
    const float* __restrict__ addsrc, int ldadd,
    int do_relu,
    __nv_bfloat16* __restrict__ Ohi, __nv_bfloat16* __restrict__ Olo, int ldo)
{
    extern __shared__ __align__(16) char smem_raw[];
    uint32_t sm0 = (uint32_t)__cvta_generic_to_shared(smem_raw);

    const int tid = threadIdx.x;
    const int wid = tid >> 5, lane = tid & 31;
    const int gid = lane >> 2, tig = lane & 3;
    const int wm = wid & 3, wn = wid >> 2;
    const int row0 = blockIdx.y * 128, col0 = blockIdx.x * 64;

    const int fr  = tid >> 2;
    const int fseg = tid & 3;
    const uint32_t fdst0 = (uint32_t)((fr * SA + fseg * 8) * 2);
    const uint32_t fdst1 = (uint32_t)(((fr + 64) * SA + fseg * 8) * 2);

    // chunk-invariant fill pointers + validity
    const int gr0 = row0 + fr, gr1 = row0 + fr + 64;
    const int gn0 = col0 + fr;
    const bool va0 = gr0 < nrows, va1 = gr1 < nrows;
    const bool vb0 = gn0 < nbrows;
    const int gk0 = fseg * 8;
    const __nv_bfloat16* pAh0 = Ahi + (size_t)(va0 ? gr0 : row0) * lda + gk0;
    const __nv_bfloat16* pAh1 = Ahi + (size_t)(va1 ? gr1 : row0) * lda + gk0;
    const __nv_bfloat16* pAl0 = Alo + (size_t)(va0 ? gr0 : row0) * lda + gk0;
    const __nv_bfloat16* pAl1 = Alo + (size_t)(va1 ? gr1 : row0) * lda + gk0;
    const __nv_bfloat16* pBh0 = Bhi + (size_t)(vb0 ? gn0 : col0) * ldb + gk0;
    const __nv_bfloat16* pBl0 = Blo + (size_t)(vb0 ? gn0 : col0) * ldb + gk0;

    const uint32_t aoffE = (uint32_t)((wm * 32 + (lane & 15)) * SA + ((lane >> 4) << 3));
    const uint32_t boffE = (uint32_t)((wn * 32 + ((lane >> 4) << 3) + (lane & 7)) * SA
                                      + (((lane >> 3) & 1) << 3));

    float acc[2][4][4];
    #pragma unroll
    for (int mt = 0; mt < 2; mt++)
        #pragma unroll
        for (int nt = 0; nt < 4; nt++)
            #pragma unroll
            for (int j = 0; j < 4; j++) acc[mt][nt][j] = 0.f;

    const int nch = K >> 5;

    // ---------- prologue: fill stage 0 ----------
    {
        uint32_t sb = sm0;
        cpa16(sb + fdst0,          pAh0, va0);
        cpa16(sb + fdst1,          pAh1, va1);
        cpa16(sb + OFF_AL + fdst0, pAl0, va0);
        cpa16(sb + OFF_AL + fdst1, pAl1, va1);
        cpa16(sb + OFF_BH + fdst0, pBh0, vb0);
        cpa16(sb + OFF_BL + fdst0, pBl0, vb0);
        CP_COMMIT();
        pAh0 += 32; pAh1 += 32; pAl0 += 32; pAl1 += 32; pBh0 += 32; pBl0 += 32;
    }

    for (int ch = 0; ch < nch; ch++) {
        CP_WAIT(0);
        __syncthreads();
        if (ch + 1 < nch) {
            uint32_t nb = sm0 + (uint32_t)((ch + 1) & 1) * STAGE_B;
            cpa16(nb + fdst0,          pAh0, va0);
            cpa16(nb + fdst1,          pAh1, va1);
            cpa16(nb + OFF_AL + fdst0, pAl0, va0);
            cpa16(nb + OFF_AL + fdst1, pAl1, va1);
            cpa16(nb + OFF_BH + fdst0, pBh0, vb0);
            cpa16(nb + OFF_BL + fdst0, pBl0, vb0);
            CP_COMMIT();
            pAh0 += 32; pAh1 += 32; pAl0 += 32; pAl1 += 32; pBh0 += 32; pBl0 += 32;
        }

        const uint32_t sb = sm0 + (uint32_t)(ch & 1) * STAGE_B;
        const uint32_t uAh = sb, uAl = sb + OFF_AL, uBh = sb + OFF_BH, uBl = sb + OFF_BL;
        #pragma unroll
        for (int ks = 0; ks < 32; ks += 16) {
            uint32_t aH[2][4], aL[2][4];
            #pragma unroll
            for (int mt = 0; mt < 2; mt++) {
                uint32_t ao = (aoffE + (uint32_t)(mt * 16 * SA + ks)) * 2u;
                ldmx4(aH[mt], uAh + ao);
                ldmx4(aL[mt], uAl + ao);
            }
            #pragma unroll
            for (int nt2 = 0; nt2 < 2; nt2++) {
                uint32_t bo = (boffE + (uint32_t)(nt2 * 16 * SA + ks)) * 2u;
                uint32_t bh[4], bl[4];
                ldmx4(bh, uBh + bo);
                ldmx4(bl, uBl + bo);
                const int n0 = nt2 * 2, n1 = nt2 * 2 + 1;
                // term-major issue: dependent MMAs on the same acc are 4 apart
                // term 1: Ah x Bh
                mma16816(acc[0][n0], aH[0], bh[0], bh[1]);
                mma16816(acc[1][n0], aH[1], bh[0], bh[1]);
                mma16816(acc[0][n1], aH[0], bh[2], bh[3]);
                mma16816(acc[1][n1], aH[1], bh[2], bh[3]);
                // term 2: Al x Bh
                mma16816(acc[0][n0], aL[0], bh[0], bh[1]);
                mma16816(acc[1][n0], aL[1], bh[0], bh[1]);
                mma16816(acc[0][n1], aL[0], bh[2], bh[3]);
                mma16816(acc[1][n1], aL[1], bh[2], bh[3]);
                // term 3: Ah x Bl
                mma16816(acc[0][n0], aH[0], bl[0], bl[1]);
                mma16816(acc[1][n0], aH[1], bl[0], bl[1]);
                mma16816(acc[0][n1], aH[0], bl[2], bl[3]);
                mma16816(acc[1][n1], aH[1], bl[2], bl[3]);
            }
        }
    }

    // ---- fused epilogue ----
    #pragma unroll
    for (int mt = 0; mt < 2; mt++) {
        #pragma unroll
        for (int nt = 0; nt < 4; nt++) {
            int gc = col0 + wn * 32 + nt * 8 + tig * 2;
            if (gc >= N) continue;
            #pragma unroll
            for (int half = 0; half < 2; half++) {
                int gr = row0 + wm * 32 + mt * 16 + gid + half * 8;
                if (gr >= nrows) continue;
                float v0 = acc[mt][nt][half * 2 + 0];
                float v1 = acc[mt][nt][half * 2 + 1];
                if (bias) {
                    v0 += (gc < biasN) ? bias[gc] : 0.f;
                    v1 += (gc + 1 < biasN) ? bias[gc + 1] : 0.f;
                }
                if (addsrc) {
                    v0 += addsrc[(size_t)gr * ldadd + gc];
                    v1 += addsrc[(size_t)gr * ldadd + gc + 1];
                }
                if (do_relu) { v0 = fmaxf(v0, 0.f); v1 = fmaxf(v1, 0.f); }
                if (C) *(float2*)&C[(size_t)gr * ldc + gc] = make_float2(v0, v1);
                if (Ohi) {
                    __nv_bfloat16 h0 = __float2bfloat16(v0);
                    __nv_bfloat16 h1 = __float2bfloat16(v1);
                    __nv_bfloat162 hp; hp.x = h0; hp.y = h1;
                    __nv_bfloat162 lp;
                    lp.x = __float2bfloat16(v0 - __bfloat162float(h0));
                    lp.y = __float2bfloat16(v1 - __bfloat162float(h1));
                    *(__nv_bfloat162*)&Ohi[(size_t)gr * ldo + gc] = hp;
                    *(__nv_bfloat162*)&Olo[(size_t)gr * ldo + gc] = lp;
                }
            }
        }
    }
}

// ---------------- el/er attention projections ----------------
__global__ void k_eler(const float* __restrict__ al, const float* __restrict__ ar) {
    int t = blockIdx.x * 256 + threadIdx.x;
    if (t >= NN * HH) return;
    int n = t >> 3, h = t & 7;
    const float* f = &g_feat[n * DD + h * 16];
    float sl = 0.f, sr = 0.f;
    #pragma unroll
    for (int i = 0; i < 16; i++) {
        float fv = f[i];
        sl = fmaf(fv, al[h * 16 + i], sl);
        sr = fmaf(fv, ar[h * 16 + i], sr);
    }
    g_el[t] = sl;
    g_er[t] = sr;
}

// ---------------- GAT aggregation ----------------
__global__ __launch_bounds__(256) void k_agg(int layer, const float* __restrict__ bias) {
    int warp = threadIdx.x >> 5;
    int lane = threadIdx.x & 31;
    int n = blockIdx.x * 8 + warp;
    if (n >= NN) return;
    int h = lane >> 2;
    int sub = lane & 3;
    float er_n = g_er[n * HH + h];
    int beg = g_rowptr[n], end = g_rowptr[n + 1];
    float m = -INFINITY, d = 0.f;
    float4 acc = {0.f, 0.f, 0.f, 0.f};
    for (int i = beg; i < end; i++) {
        int s = g_csr_src[i];
        float e = g_el[s * HH + h] + er_n;
        e = (e > 0.f) ? e : NEG_SLOPE * e;
        float4 f = *(const float4*)(&g_feat[s * DD + h * 16 + sub * 4]);
        float mn = fmaxf(m, e);
        float sc = __expf(m - mn);
        float w  = __expf(e - mn);
        d = fmaf(d, sc, w);
        acc.x = fmaf(acc.x, sc, w * f.x);
        acc.y = fmaf(acc.y, sc, w * f.y);
        acc.z = fmaf(acc.z, sc, w * f.z);
        acc.w = fmaf(acc.w, sc, w * f.w);
        m = mn;
    }
    float inv = (d > 0.f) ? (1.f / d) : 0.f;
    int off = h * 16 + sub * 4;
    float4 hv = *(const float4*)(&g_Xcat[(size_t)n * CATD + layer * DD + off]);
    float4 bv = *(const float4*)(&bias[off]);
    float4 o;
    o.x = hv.x + acc.x * inv + bv.x;
    o.y = hv.y + acc.y * inv + bv.y;
    o.z = hv.z + acc.z * inv + bv.z;
    o.w = hv.w + acc.w * inv + bv.w;
    *(float4*)(&g_h1[n * DD + off]) = o;
}

// ---------------- BatchNorm ----------------
__global__ void k_bnstats(const float* __restrict__ src, int ld) {
    int c = threadIdx.x;
    int r0 = blockIdx.x * 256;
    float s = 0.f, q = 0.f;
    for (int r = 0; r < 256; r++) {
        int row = r0 + r;
        if (row >= NN) break;
        float v = src[(size_t)row * ld + c];
        s += v;
        q = fmaf(v, v, q);
    }
    atomicAdd(&g_stats[c], s);
    atomicAdd(&g_stats[128 + c], q);
}
__global__ void k_bncoef(const float* __restrict__ g, const float* __restrict__ b) {
    int c = threadIdx.x;
    if (c >= 128) return;
    float mu = g_stats[c] / (float)NN;
    float var = g_stats[128 + c] / (float)NN - mu * mu;
    float a = g[c] * rsqrtf(var + EPSV);
    g_coef[c] = a;
    g_coef[128 + c] = b[c] - mu * a;
    g_stats[c] = 0.f;
    g_stats[128 + c] = 0.f;
}
__global__ void k_bnapply(const float* __restrict__ src, int lds,
                          float* __restrict__ dst, int ldd,
                          __nv_bfloat16* __restrict__ oh, __nv_bfloat16* __restrict__ ol, int ldo) {
    int t = blockIdx.x * 256 + threadIdx.x;
    if (t >= NN * DD) return;
    int n = t >> 7, c = t & 127;
    float v = fmaf(g_coef[c], src[(size_t)n * lds + c], g_coef[128 + c]);
    dst[(size_t)n * ldd + c] = v;
    __nv_bfloat16 h = __float2bfloat16(v);
    oh[(size_t)n * ldo + c] = h;
    ol[(size_t)n * ldo + c] = __float2bfloat16(v - __bfloat162float(h));
}

// ---------------- decoder tail ----------------
__global__ __launch_bounds__(256) void k_dec(const float* __restrict__ w2,
                                             float* __restrict__ out) {
    int warp = threadIdx.x >> 5;
    int lane = threadIdx.x & 31;
    int n = blockIdx.x * 8 + warp;
    if (n >= NN) return;
    int c0 = lane * 4;
    float4 z4 = *(const float4*)(&g_z[n * DD + c0]);
    float v = 0.f;
    #pragma unroll
    for (int j = 0; j < 4; j++) {
        int c = c0 + j;
        float zz = (j == 0) ? z4.x : (j == 1) ? z4.y : (j == 2) ? z4.z : z4.w;
        float hv = fmaf(g_coef[c], zz, g_coef[128 + c]);
        hv = fmaxf(hv, 0.f);
        v = fmaf(hv, w2[c], v);
    }
    #pragma unroll
    for (int o = 16; o > 0; o >>= 1)
        v += __shfl_down_sync(0xFFFFFFFFu, v, o);
    if (lane == 0) out[n] = v;
}

// ---------------- host orchestration ----------------
static inline int cdiv(int a, int b) { return (a + b - 1) / b; }

extern "C" void kernel_launch(void* const* d_in, const int* in_sizes, int n_in,
                              void* d_out, int out_size) {
    const float* x      = (const float*)d_in[0];
    const int*   src    = (const int*)  d_in[1];
    const int*   dst    = (const int*)  d_in[2];
    const float* W_emb  = (const float*)d_in[3];
    const float* b_emb  = (const float*)d_in[4];
    const float* gat_W  = (const float*)d_in[5];
    const float* attn_l = (const float*)d_in[6];
    const float* attn_r = (const float*)d_in[7];
    const float* gat_b  = (const float*)d_in[8];
    const float* bn1_g  = (const float*)d_in[9];
    const float* bn1_b  = (const float*)d_in[10];
    const float* ff_W1  = (const float*)d_in[11];
    const float* ff_b1  = (const float*)d_in[12];
    const float* ff_W2  = (const float*)d_in[13];
    const float* ff_b2  = (const float*)d_in[14];
    const float* bn2_g  = (const float*)d_in[15];
    const float* bn2_b  = (const float*)d_in[16];
    const float* dec_W1 = (const float*)d_in[17];
    const float* dec_bn_g = (const float*)d_in[18];
    const float* dec_bn_b = (const float*)d_in[19];
    const float* dec_W2 = (const float*)d_in[20];
    float* out = (float*)d_out;

    float *p_xcat, *p_feat, *p_h1, *p_h2, *p_z;
    cudaGetSymbolAddress((void**)&p_xcat, g_Xcat);
    cudaGetSymbolAddress((void**)&p_feat, g_feat);
    cudaGetSymbolAddress((void**)&p_h1,   g_h1);
    cudaGetSymbolAddress((void**)&p_h2,   g_h2);
    cudaGetSymbolAddress((void**)&p_z,    g_z);
    __nv_bfloat16 *xh, *xl, *Xh, *Xl, *hbh, *hbl, *th, *tl;
    __nv_bfloat16 *WembTh, *WembTl, *gatWTh, *gatWTl, *W1Th, *W1Tl, *W2Th, *W2Tl, *dW1Th, *dW1Tl;
    cudaGetSymbolAddress((void**)&xh,  gb_xh);   cudaGetSymbolAddress((void**)&xl,  gb_xl);
    cudaGetSymbolAddress((void**)&Xh,  gb_Xh);   cudaGetSymbolAddress((void**)&Xl,  gb_Xl);
    cudaGetSymbolAddress((void**)&hbh, gb_hbh);  cudaGetSymbolAddress((void**)&hbl, gb_hbl);
    cudaGetSymbolAddress((void**)&th,  gb_th);   cudaGetSymbolAddress((void**)&tl,  gb_tl);
    cudaGetSymbolAddress((void**)&WembTh, gb_WembT_h); cudaGetSymbolAddress((void**)&WembTl, gb_WembT_l);
    cudaGetSymbolAddress((void**)&gatWTh, gb_gatWT_h); cudaGetSymbolAddress((void**)&gatWTl, gb_gatWT_l);
    cudaGetSymbolAddress((void**)&W1Th, gb_W1T_h);     cudaGetSymbolAddress((void**)&W1Tl, gb_W1T_l);
    cudaGetSymbolAddress((void**)&W2Th, gb_W2T_h);     cudaGetSymbolAddress((void**)&W2Tl, gb_W2T_l);
    cudaGetSymbolAddress((void**)&dW1Th, gb_dW1T_h);   cudaGetSymbolAddress((void**)&dW1Tl, gb_dW1T_l);

    cudaFuncSetAttribute(tgemm, cudaFuncAttributeMaxDynamicSharedMemorySize, SMEM_REQ);

    const int egrid = cdiv(EE, 256);
    const int ngrid = cdiv(NN, 256);
    const int mt = cdiv(NN, 128);   // 313 M tiles

    // ---- conversions first, then embed GEMM early ----
    k_cvt<<<cdiv(NN * IND, 256), 256>>>(x, xh, xl, NN * IND);
    k_wt_all<<<dim3(112, 11), 256>>>(W_emb, gat_W, ff_W1, ff_W2, dec_W1);
    k_zero_deg<<<ngrid, 256>>>();

    tgemm<<<dim3(2, mt), 256, SMEM_REQ>>>(xh, xl, IND, WembTh, WembTl, IND,
        NN, IND, DD, DD, p_xcat, CATD, b_emb, DD, nullptr, 0, 0, Xh, Xl, CATD);

    // ---- CSR build ----
    k_hist<<<egrid, 256>>>(dst);
    k_scan<<<1, 1024>>>();
    k_scatter<<<egrid, 256>>>(src, dst);

    for (int l = 0; l < LL; l++) {
        // feat = h @ gat_W[l]
        tgemm<<<dim3(2, mt), 256, SMEM_REQ>>>(Xh + l * DD, Xl + l * DD, CATD,
            gatWTh + l * DD * DD, gatWTl + l * DD * DD, DD,
            NN, DD, DD, DD, p_feat, DD, nullptr, 0, nullptr, 0, 0, nullptr, nullptr, 0);
        k_eler<<<cdiv(NN * HH, 256), 256>>>(attn_l + l * DD, attn_r + l * DD);
        k_agg<<<cdiv(NN, 8), 256>>>(l, gat_b + l * DD);
        // BN1 -> hb
        k_bnstats<<<cdiv(NN, 256), 128>>>(p_h1, DD);
        k_bncoef<<<1, 128>>>(bn1_g + l * DD, bn1_b + l * DD);
        k_bnapply<<<cdiv(NN * DD, 256), 256>>>(p_h1, DD, p_feat, DD, hbh, hbl, DD);
        // t = relu(hb @ W1 + b1)
        tgemm<<<dim3(4, mt), 256, SMEM_REQ>>>(hbh, hbl, DD,
            W1Th + l * FFP * DD, W1Tl + l * FFP * DD, DD,
            NN, DD, FFP, FFP, nullptr, 0, ff_b1 + l * FFD, FFD, nullptr, 0, 1, th, tl, FFP);
        // h2 = t @ W2 + b2 + hb
        tgemm<<<dim3(2, mt), 256, SMEM_REQ>>>(th, tl, FFP,
            W2Th + l * DD * FFP, W2Tl + l * DD * FFP, FFP,
            NN, FFP, DD, DD, p_h2, DD, ff_b2 + l * DD, DD, p_feat, DD, 0, nullptr, nullptr, 0);
        // BN2 -> Xcat slice l+1
        k_bnstats<<<cdiv(NN, 256), 128>>>(p_h2, DD);
        k_bncoef<<<1, 128>>>(bn2_g + l * DD, bn2_b + l * DD);
        k_bnapply<<<cdiv(NN * DD, 256), 256>>>(p_h2, DD, p_xcat + (l + 1) * DD, CATD,
                                               Xh + (l + 1) * DD, Xl + (l + 1) * DD, CATD);
    }

    // ---- decoder ----
    tgemm<<<dim3(2, mt), 256, SMEM_REQ>>>(Xh, Xl, CATD, dW1Th, dW1Tl, CATD,
        NN, CATD, DD, DD, p_z, DD, nullptr, 0, nullptr, 0, 0, nullptr, nullptr, 0);
    k_bnstats<<<cdiv(NN, 256), 128>>>(p_z, DD);
    k_bncoef<<<1, 128>>>(dec_bn_g, dec_bn_b);
    k_dec<<<cdiv(NN, 8), 256>>>(dec_W2, out);
}